// round 9
// baseline (speedup 1.0000x reference)
#include <cuda_runtime.h>
#include <math.h>

#define Bq 4096
#define Sq 512
#define NT 256
#define NB 128
#define RPB 32
#define KST 76               // unified k stride: h[0:64) | x[64:75) | pad
#define HBUFSZ (RPB*KST)     // 2432 floats per h|x buffer

typedef unsigned long long ull;

// shared layout (float offsets)
#define O_WA   0                         // wa [38 kk][64 gt] float4 = 9728
#define O_WB   (O_WA + 38*64*4)          // wb same                  = 9728
#define O_PRE4 (O_WB + 38*64*4)          // pre4 [32][64] float4     = 8192
#define O_HB   (O_PRE4 + 8192)           // 2 * [32][KST]            = 4864
#define O_WOUT (O_HB + 2*HBUFSZ)         // 128
#define O_SC   (O_WOUT + 128)
#define O_ISC  (O_SC + 32)
#define SM_TOTAL (O_ISC + 32)
#define SMEM_BYTES (SM_TOTAL*4)          // ~131 KB

__device__ __forceinline__ float sigf(float x){ return 1.0f/(1.0f+__expf(-x)); }
__device__ __forceinline__ float tanh_f(float x){ return 2.0f/(1.0f+__expf(-2.0f*x)) - 1.0f; }

__device__ __forceinline__ void ffma2(ull &d, ull a, ull b){
    asm("fma.rn.f32x2 %0, %1, %2, %0;" : "+l"(d) : "l"(a), "l"(b));
}
__device__ __forceinline__ float fold2(ull v){
    float2 f; asm("mov.b64 {%0,%1}, %2;" : "=f"(f.x), "=f"(f.y) : "l"(v));
    return f.x + f.y;
}
__device__ __forceinline__ void pbar(int id){
    asm volatile("bar.sync %0, 64;" :: "r"(id) : "memory");
}

__global__ void __launch_bounds__(NT,1)
deepar_kernel(const float* __restrict__ target,
              const float* __restrict__ covar,
              const int*   __restrict__ cats,
              const float* __restrict__ scale,
              const float* __restrict__ e0,
              const float* __restrict__ e1,
              const float* __restrict__ e2,
              const float* __restrict__ e3,
              const float* __restrict__ w_ih,
              const float* __restrict__ w_hh,
              const float* __restrict__ bias,
              const float* __restrict__ w_out,
              const float* __restrict__ b_out,
              float* __restrict__ out)
{
    extern __shared__ float sm[];
    float* wa_s   = sm + O_WA;
    float* wb_s   = sm + O_WB;
    float* pre4_s = sm + O_PRE4;
    float* hbuf   = sm + O_HB;
    float* wout_s = sm + O_WOUT;
    float* sc_s   = sm + O_SC;
    float* isc_s  = sm + O_ISC;
    float* sx_s   = sm + O_WA;     // alias: static_x [32][66], pre-phase only

    const int tid  = threadIdx.x;
    const int row0 = blockIdx.x * RPB;

    // ---- phase 0: stage static_x into sx_s (aliases wa_s; weights packed later) ----
    for (int e = tid; e < RPB*65; e += NT){
        int r = e / 65, j = e - r*65;
        int b = row0 + r;
        float v;
        if (j < 64){
            int tsel = j >> 4, jj = j & 15;
            int c = cats[b*4 + tsel];
            const float* et = (tsel==0)?e0:(tsel==1)?e1:(tsel==2)?e2:e3;
            v = et[c*16 + jj];
        } else {
            v = log1pf(scale[b]);
        }
        sx_s[r*66 + j] = v;
    }
    __syncthreads();

    // ---- mapping: pair p = tid>>6 owns rows 8p..8p+7; gt = tid&63 ----
    const int gt    = tid & 63;
    const int pid   = tid >> 6;        // 0..3
    const int rbase = pid * 8;
    const int pairLane = gt;

    // ---- pre (registers, prologue only) then spill to smem as float4 ----
    {
        float accp[8][4];
        #pragma unroll
        for (int tp = 0; tp < 4; tp++){
            float bv = bias[tp*64 + gt];
            #pragma unroll
            for (int j = 0; j < 8; j++) accp[j][tp] = bv;
        }
        for (int k = 0; k < 65; k++){
            const float* wr = w_ih + (11+k)*256 + gt;
            float w0 = wr[0], w1 = wr[64], w2 = wr[128], w3 = wr[192];
            #pragma unroll
            for (int j = 0; j < 8; j++){
                float xv = sx_s[(rbase+j)*66 + k];
                accp[j][0] = fmaf(xv, w0, accp[j][0]);
                accp[j][1] = fmaf(xv, w1, accp[j][1]);
                accp[j][2] = fmaf(xv, w2, accp[j][2]);
                accp[j][3] = fmaf(xv, w3, accp[j][3]);
            }
        }
        __syncthreads();   // sx readers done before wa_s overwrite / pre4 write
        #pragma unroll
        for (int j = 0; j < 8; j++){
            float4 p; p.x=accp[j][0]; p.y=accp[j][1]; p.z=accp[j][2]; p.w=accp[j][3];
            *(float4*)(pre4_s + ((rbase+j)*64 + gt)*4) = p;
        }
    }

    // ---- pack weights: wa[kk][gt] = {i:kpair, f:kpair}, wb = {g:kpair, o:kpair} ----
    for (int idx = tid; idx < 38*64; idx += NT){
        int kk = idx >> 6, g = idx & 63;
        int k0 = 2*kk, k1 = 2*kk + 1;
        #define WK(k,c) ((k) < 64 ? w_hh[(k)*256 + (c)] : ((k) < 75 ? w_ih[((k)-64)*256 + (c)] : 0.0f))
        float4 a4, b4;
        a4.x = WK(k0, g);        a4.y = WK(k1, g);
        a4.z = WK(k0, 64 + g);   a4.w = WK(k1, 64 + g);
        b4.x = WK(k0, 128 + g);  b4.y = WK(k1, 128 + g);
        b4.z = WK(k0, 192 + g);  b4.w = WK(k1, 192 + g);
        #undef WK
        *(float4*)(wa_s + idx*4) = a4;
        *(float4*)(wb_s + idx*4) = b4;
    }
    if (tid < 128) wout_s[tid] = w_out[tid];
    if (tid < RPB){
        float s = scale[row0 + tid];
        sc_s[tid]  = s;
        isc_s[tid] = 1.0f / fmaxf(s, 1e-4f);
    }
    for (int i = tid; i < 2*HBUFSZ; i += NT) hbuf[i] = 0.0f;
    __syncthreads();

    // ---- x ownership: 96 slots (8 rows x 12 j) per pair; lane s=pairLane, s2=pairLane+64 ----
    int xrow0_ = 0, xj0_ = 0, xb0_ = 0;
    int xrow1_ = 0, xj1_ = 0, xb1_ = 0;
    const bool xown1 = (pairLane < 32);     // second slot for lanes 0..31
    float xreg0 = 0.0f, xreg1 = 0.0f;
    {
        int s0 = pairLane;
        xrow0_ = rbase + s0/12; xj0_ = s0%12; xb0_ = row0 + xrow0_;
        float v0 = (xj0_>=1 && xj0_<=10) ? covar[(xb0_*Sq + 0)*10 + (xj0_-1)] : 0.0f;
        hbuf[1*HBUFSZ + xrow0_*KST + 64 + xj0_] = v0;
        if (xown1){
            int s1 = pairLane + 64;
            xrow1_ = rbase + s1/12; xj1_ = s1%12; xb1_ = row0 + xrow1_;
            float v1 = (xj1_>=1 && xj1_<=10) ? covar[(xb1_*Sq + 0)*10 + (xj1_-1)] : 0.0f;
            hbuf[1*HBUFSZ + xrow1_*KST + 64 + xj1_] = v1;
        }
    }
    // head ownership: pairLane 48..63 -> (8 rows x 2 outputs)
    const bool hown = (pairLane >= 48);
    const int  hr_  = rbase + ((pairLane - 48) >> 1);
    const int  hws  = pairLane & 1;
    __syncthreads();

    const int barid = pid + 1;
    float creg[8] = {0,0,0,0,0,0,0,0};

    for (int t = 0; t < Sq; t++){
        pbar(barid);   // pair-local: h(t-1)/x(t) of rows rbase..rbase+7 visible
        const float* hb = hbuf + ((t+1)&1)*HBUFSZ;   // h(t-1) | x(t)

        // head for step t-1
        if (hown && t > 0){
            const float* hr = hb + hr_*KST;
            float a0=0.f,a1=0.f,a2=0.f,a3=0.f;
            #pragma unroll 8
            for (int k = 0; k < 64; k += 4){
                a0 = fmaf(hr[k],   wout_s[2*k     + hws], a0);
                a1 = fmaf(hr[k+1], wout_s[2*(k+1) + hws], a1);
                a2 = fmaf(hr[k+2], wout_s[2*(k+2) + hws], a2);
                a3 = fmaf(hr[k+3], wout_s[2*(k+3) + hws], a3);
            }
            float a = (a0+a1)+(a2+a3) + b_out[hws];
            float sp = (a > 15.0f) ? a : log1pf(__expf(a));
            sp += 1e-4f;
            int b = row0 + hr_;
            if (hws == 0) out[b*Sq + (t-1)] = sp * sc_s[hr_];
            else          out[Bq*Sq + b*Sq + (t-1)] = sp;
        }
        // prefetch x(t+1)
        if (t+1 < Sq){
            if (xj0_ == 0)       xreg0 = target[xb0_*Sq + t] * isc_s[xrow0_];
            else if (xj0_ <= 10) xreg0 = covar[(xb0_*Sq + t+1)*10 + (xj0_-1)];
            else                 xreg0 = 0.0f;
            if (xown1){
                if (xj1_ == 0)       xreg1 = target[xb1_*Sq + t] * isc_s[xrow1_];
                else if (xj1_ <= 10) xreg1 = covar[(xb1_*Sq + t+1)*10 + (xj1_-1)];
                else                 xreg1 = 0.0f;
            }
        }

        // ================= GEMM: 8 rows x 4 gate types =================
        ull acc[8][4];
        #pragma unroll
        for (int j = 0; j < 8; j++)
            #pragma unroll
            for (int tp = 0; tp < 4; tp++) acc[j][tp] = 0ull;

        #pragma unroll
        for (int kk2 = 0; kk2 < 19; kk2++){
            ulonglong2 wa0 = *(const ulonglong2*)(wa_s + ((2*kk2  )*64 + gt)*4);
            ulonglong2 wb0 = *(const ulonglong2*)(wb_s + ((2*kk2  )*64 + gt)*4);
            ulonglong2 wa1 = *(const ulonglong2*)(wa_s + ((2*kk2+1)*64 + gt)*4);
            ulonglong2 wb1 = *(const ulonglong2*)(wb_s + ((2*kk2+1)*64 + gt)*4);
            #pragma unroll
            for (int j = 0; j < 8; j++){
                ulonglong2 hv = *(const ulonglong2*)(hb + (rbase+j)*KST + kk2*4);
                ffma2(acc[j][0], hv.x, wa0.x);
                ffma2(acc[j][1], hv.x, wa0.y);
                ffma2(acc[j][2], hv.x, wb0.x);
                ffma2(acc[j][3], hv.x, wb0.y);
                ffma2(acc[j][0], hv.y, wa1.x);
                ffma2(acc[j][1], hv.y, wa1.y);
                ffma2(acc[j][2], hv.y, wb1.x);
                ffma2(acc[j][3], hv.y, wb1.y);
            }
        }

        // ================= fused LSTM cell (pre from smem) + h store =================
        {
            float* hw = hbuf + (t&1)*HBUFSZ;
            #pragma unroll
            for (int j = 0; j < 8; j++){
                float4 p = *(const float4*)(pre4_s + ((rbase+j)*64 + gt)*4);
                float gi = fold2(acc[j][0]) + p.x;
                float gf = fold2(acc[j][1]) + p.y;
                float gg = fold2(acc[j][2]) + p.z;
                float go = fold2(acc[j][3]) + p.w;
                float i = sigf(gi);
                float f = sigf(gf);
                float g = tanh_f(gg);
                float o = sigf(go);
                float c = fmaf(f, creg[j], i*g);
                creg[j] = c;
                hw[(rbase+j)*KST + gt] = o * tanh_f(c);
            }
            hw[xrow0_*KST + 64 + xj0_] = xreg0;
            if (xown1) hw[xrow1_*KST + 64 + xj1_] = xreg1;
        }
    }

    // final head for t = Sq-1
    pbar(barid);
    if (hown){
        const float* hr = hbuf + ((Sq-1)&1)*HBUFSZ + hr_*KST;
        float a0=0.f,a1=0.f,a2=0.f,a3=0.f;
        #pragma unroll 8
        for (int k = 0; k < 64; k += 4){
            a0 = fmaf(hr[k],   wout_s[2*k     + hws], a0);
            a1 = fmaf(hr[k+1], wout_s[2*(k+1) + hws], a1);
            a2 = fmaf(hr[k+2], wout_s[2*(k+2) + hws], a2);
            a3 = fmaf(hr[k+3], wout_s[2*(k+3) + hws], a3);
        }
        float a = (a0+a1)+(a2+a3) + b_out[hws];
        float sp = (a > 15.0f) ? a : log1pf(__expf(a));
        sp += 1e-4f;
        int b = row0 + hr_;
        if (hws == 0) out[b*Sq + (Sq-1)] = sp * sc_s[hr_];
        else          out[Bq*Sq + b*Sq + (Sq-1)] = sp;
    }
}

extern "C" void kernel_launch(void* const* d_in, const int* in_sizes, int n_in,
                              void* d_out, int out_size)
{
    (void)in_sizes; (void)n_in; (void)out_size;
    cudaFuncSetAttribute(deepar_kernel,
                         cudaFuncAttributeMaxDynamicSharedMemorySize, SMEM_BYTES);
    deepar_kernel<<<NB, NT, SMEM_BYTES>>>(
        (const float*)d_in[0],   // target
        (const float*)d_in[1],   // covariates
        (const int*)  d_in[2],   // static_cats
        (const float*)d_in[3],   // scale
        (const float*)d_in[4],   // emb0
        (const float*)d_in[5],   // emb1
        (const float*)d_in[6],   // emb2
        (const float*)d_in[7],   // emb3
        (const float*)d_in[8],   // w_ih
        (const float*)d_in[9],   // w_hh
        (const float*)d_in[10],  // bias
        (const float*)d_in[11],  // w_out
        (const float*)d_in[12],  // b_out
        (float*)d_out);
}

// round 10
// speedup vs baseline: 1.2210x; 1.2210x over previous
#include <cuda_runtime.h>
#include <math.h>

#define Bq 4096
#define Sq 512
#define NT 512
#define NB 128
#define RPB 32
#define KST 76               // unified k stride: h[0:64) | x[64:75) | pad
#define HBUFSZ (RPB*KST)     // 2432 floats per h|x buffer

typedef unsigned long long ull;

// shared layout (float offsets)
#define O_WA   0                         // wa [38 kk][64 gt] float4 = 9728
#define O_WB   (O_WA + 9728)             // wb same                  = 9728
#define O_PRE4 (O_WB + 9728)             // pre4 [32][64] float4     = 8192
#define O_EX   (O_PRE4 + 8192)           // ex [2][32][64] float4    = 16384
#define O_HB   (O_EX + 16384)            // 2 * [32][KST]            = 4864
#define O_WOUT (O_HB + 2*HBUFSZ)         // 128
#define O_SC   (O_WOUT + 128)
#define O_ISC  (O_SC + 32)
#define SM_TOTAL (O_ISC + 32)
#define SMEM_BYTES (SM_TOTAL*4)          // ~196 KB

__device__ __forceinline__ float sigf(float x){ return 1.0f/(1.0f+__expf(-x)); }
__device__ __forceinline__ float tanh_f(float x){ return 2.0f/(1.0f+__expf(-2.0f*x)) - 1.0f; }

__device__ __forceinline__ void ffma2(ull &d, ull a, ull b){
    asm("fma.rn.f32x2 %0, %1, %2, %0;" : "+l"(d) : "l"(a), "l"(b));
}
__device__ __forceinline__ float fold2(ull v){
    float2 f; asm("mov.b64 {%0,%1}, %2;" : "=f"(f.x), "=f"(f.y) : "l"(v));
    return f.x + f.y;
}
__device__ __forceinline__ void gbar(int id){
    asm volatile("bar.sync %0, 128;" :: "r"(id) : "memory");
}

__global__ void __launch_bounds__(NT,1)
deepar_kernel(const float* __restrict__ target,
              const float* __restrict__ covar,
              const int*   __restrict__ cats,
              const float* __restrict__ scale,
              const float* __restrict__ e0,
              const float* __restrict__ e1,
              const float* __restrict__ e2,
              const float* __restrict__ e3,
              const float* __restrict__ w_ih,
              const float* __restrict__ w_hh,
              const float* __restrict__ bias,
              const float* __restrict__ w_out,
              const float* __restrict__ b_out,
              float* __restrict__ out)
{
    extern __shared__ float sm[];
    float* wa_s   = sm + O_WA;
    float* wb_s   = sm + O_WB;
    float* pre4_s = sm + O_PRE4;
    float* ex_s   = sm + O_EX;
    float* hbuf   = sm + O_HB;
    float* wout_s = sm + O_WOUT;
    float* sc_s   = sm + O_SC;
    float* isc_s  = sm + O_ISC;
    float* sx_s   = sm + O_WA;     // alias: static_x [32][66], pre-phase only

    const int tid  = threadIdx.x;
    const int row0 = blockIdx.x * RPB;

    // ---- stage static_x into sx_s ----
    for (int e = tid; e < RPB*65; e += NT){
        int r = e / 65, j = e - r*65;
        int b = row0 + r;
        float v;
        if (j < 64){
            int tsel = j >> 4, jj = j & 15;
            int c = cats[b*4 + tsel];
            const float* et = (tsel==0)?e0:(tsel==1)?e1:(tsel==2)?e2:e3;
            v = et[c*16 + jj];
        } else {
            v = log1pf(scale[b]);
        }
        sx_s[r*66 + j] = v;
    }
    __syncthreads();

    // ---- mapping: group (128 thr) owns 8 rows; thread = gt x k-half ----
    const int grp   = tid >> 7;          // 0..3
    const int gLane = tid & 127;
    const int kh    = gLane >> 6;        // k-half
    const int gt    = gLane & 63;        // cell column
    const int rbase = grp * 8;

    // ---- pre = bias + static_x @ w_ih[11:76] (kh==0 threads only, one-time) ----
    {
        float accp[8][4];
        if (kh == 0){
            #pragma unroll
            for (int tp = 0; tp < 4; tp++){
                float bv = bias[tp*64 + gt];
                #pragma unroll
                for (int j = 0; j < 8; j++) accp[j][tp] = bv;
            }
            for (int k = 0; k < 65; k++){
                const float* wr = w_ih + (11+k)*256 + gt;
                float w0 = wr[0], w1 = wr[64], w2 = wr[128], w3 = wr[192];
                #pragma unroll
                for (int j = 0; j < 8; j++){
                    float xv = sx_s[(rbase+j)*66 + k];
                    accp[j][0] = fmaf(xv, w0, accp[j][0]);
                    accp[j][1] = fmaf(xv, w1, accp[j][1]);
                    accp[j][2] = fmaf(xv, w2, accp[j][2]);
                    accp[j][3] = fmaf(xv, w3, accp[j][3]);
                }
            }
        }
        __syncthreads();   // all sx reads done before weight pack overwrites
        if (kh == 0){
            #pragma unroll
            for (int j = 0; j < 8; j++){
                float4 p; p.x=accp[j][0]; p.y=accp[j][1]; p.z=accp[j][2]; p.w=accp[j][3];
                *(float4*)(pre4_s + ((rbase+j)*64 + gt)*4) = p;
            }
        }
    }

    // ---- pack weights: wa[kk][gt]={i:kpair,f:kpair}, wb={g:kpair,o:kpair} ----
    for (int idx = tid; idx < 38*64; idx += NT){
        int kk = idx >> 6, g = idx & 63;
        int k0 = 2*kk, k1 = 2*kk + 1;
        #define WK(k,c) ((k) < 64 ? w_hh[(k)*256 + (c)] : ((k) < 75 ? w_ih[((k)-64)*256 + (c)] : 0.0f))
        float4 a4, b4;
        a4.x = WK(k0, g);        a4.y = WK(k1, g);
        a4.z = WK(k0, 64 + g);   a4.w = WK(k1, 64 + g);
        b4.x = WK(k0, 128 + g);  b4.y = WK(k1, 128 + g);
        b4.z = WK(k0, 192 + g);  b4.w = WK(k1, 192 + g);
        #undef WK
        *(float4*)(wa_s + idx*4) = a4;
        *(float4*)(wb_s + idx*4) = b4;
    }
    if (tid < 128) wout_s[tid] = w_out[tid];
    if (tid < RPB){
        float s = scale[row0 + tid];
        sc_s[tid]  = s;
        isc_s[tid] = 1.0f / fmaxf(s, 1e-4f);
    }
    for (int i = tid; i < 2*HBUFSZ; i += NT) hbuf[i] = 0.0f;
    __syncthreads();

    // ---- x ownership: 96 slots (8 rows x 12 j) per group, gLane 0..95 ----
    int xrow = 0, xj = 0, xb = 0;
    const bool xown = (gLane < 96);
    float xreg = 0.0f;
    if (xown){
        xrow = rbase + gLane/12;
        xj   = gLane % 12;
        xb   = row0 + xrow;
        float v = 0.0f;
        if (xj >= 1 && xj <= 10) v = covar[(xb*Sq + 0)*10 + (xj-1)];
        hbuf[1*HBUFSZ + xrow*KST + 64 + xj] = v;   // x(0)
    }
    // head: gLane 96..111 -> (8 rows x 2 outputs)
    const bool hown = (gLane >= 96) && (gLane < 112);
    const int  hr_  = rbase + ((gLane - 96) >> 1);
    const int  hws  = gLane & 1;
    __syncthreads();

    const int barid = grp + 1;
    float creg[4] = {0,0,0,0};
    const int rcell = rbase + kh*4;   // cell rows rcell..rcell+3

    for (int t = 0; t < Sq; t++){
        gbar(barid);   // group-local: h(t-1)/x(t) rows visible; ex reads done
        const float* hb = hbuf + ((t+1)&1)*HBUFSZ;   // h(t-1) | x(t)

        // head for step t-1 (stable hb rows of this group)
        if (hown && t > 0){
            const float* hr = hb + hr_*KST;
            float a0=0.f,a1=0.f,a2=0.f,a3=0.f;
            #pragma unroll 8
            for (int k = 0; k < 64; k += 4){
                a0 = fmaf(hr[k],   wout_s[2*k     + hws], a0);
                a1 = fmaf(hr[k+1], wout_s[2*(k+1) + hws], a1);
                a2 = fmaf(hr[k+2], wout_s[2*(k+2) + hws], a2);
                a3 = fmaf(hr[k+3], wout_s[2*(k+3) + hws], a3);
            }
            float a = (a0+a1)+(a2+a3) + b_out[hws];
            float sp = (a > 15.0f) ? a : log1pf(__expf(a));
            sp += 1e-4f;
            int b = row0 + hr_;
            if (hws == 0) out[b*Sq + (t-1)] = sp * sc_s[hr_];
            else          out[Bq*Sq + b*Sq + (t-1)] = sp;
        }
        // prefetch x(t+1)
        if (xown && t+1 < Sq){
            if (xj == 0)       xreg = target[xb*Sq + t] * isc_s[xrow];
            else if (xj <= 10) xreg = covar[(xb*Sq + t+1)*10 + (xj-1)];
            else               xreg = 0.0f;
        }

        // ============ GEMM: 8 rows x 4 types over this thread's k-half ============
        ull acc[8][4];
        #pragma unroll
        for (int j = 0; j < 8; j++)
            #pragma unroll
            for (int tp = 0; tp < 4; tp++) acc[j][tp] = 0ull;

        #define GSTEP(kk2) { \
            ulonglong2 wa0 = *(const ulonglong2*)(wa_s + ((2*(kk2)  )*64 + gt)*4); \
            ulonglong2 wb0 = *(const ulonglong2*)(wb_s + ((2*(kk2)  )*64 + gt)*4); \
            ulonglong2 wa1 = *(const ulonglong2*)(wa_s + ((2*(kk2)+1)*64 + gt)*4); \
            ulonglong2 wb1 = *(const ulonglong2*)(wb_s + ((2*(kk2)+1)*64 + gt)*4); \
            _Pragma("unroll") \
            for (int j = 0; j < 8; j++){ \
                ulonglong2 hv = *(const ulonglong2*)(hb + (rbase+j)*KST + (kk2)*4); \
                ffma2(acc[j][0], hv.x, wa0.x); \
                ffma2(acc[j][1], hv.x, wa0.y); \
                ffma2(acc[j][2], hv.x, wb0.x); \
                ffma2(acc[j][3], hv.x, wb0.y); \
                ffma2(acc[j][0], hv.y, wa1.x); \
                ffma2(acc[j][1], hv.y, wa1.y); \
                ffma2(acc[j][2], hv.y, wb1.x); \
                ffma2(acc[j][3], hv.y, wb1.y); \
            } }

        if (kh == 0){
            #pragma unroll
            for (int kk2 = 0; kk2 < 10; kk2++) GSTEP(kk2)
        } else {
            #pragma unroll
            for (int kk2 = 10; kk2 < 19; kk2++) GSTEP(kk2)
        }
        #undef GSTEP

        // store partial gates to exchange
        #pragma unroll
        for (int j = 0; j < 8; j++){
            float4 p;
            p.x = fold2(acc[j][0]);
            p.y = fold2(acc[j][1]);
            p.z = fold2(acc[j][2]);
            p.w = fold2(acc[j][3]);
            *(float4*)(ex_s + ((kh*32 + rbase+j)*64 + gt)*4) = p;
        }
        gbar(barid);   // partials visible within group

        // ============ cell: combine halves + pre, update c, store h ============
        {
            float* hw = hbuf + (t&1)*HBUFSZ;
            #pragma unroll
            for (int j = 0; j < 4; j++){
                int r = rcell + j;
                float4 pa = *(const float4*)(ex_s + ((     r)*64 + gt)*4);
                float4 pb = *(const float4*)(ex_s + ((32 + r)*64 + gt)*4);
                float4 pp = *(const float4*)(pre4_s + (r*64 + gt)*4);
                float gi = pa.x + pb.x + pp.x;
                float gf = pa.y + pb.y + pp.y;
                float gg = pa.z + pb.z + pp.z;
                float go = pa.w + pb.w + pp.w;
                float i = sigf(gi);
                float f = sigf(gf);
                float g = tanh_f(gg);
                float o = sigf(go);
                float c = fmaf(f, creg[j], i*g);
                creg[j] = c;
                hw[r*KST + gt] = o * tanh_f(c);
            }
            if (xown) hw[xrow*KST + 64 + xj] = xreg;   // x(t+1)
        }
    }

    // final head for t = Sq-1
    gbar(barid);
    if (hown){
        const float* hr = hbuf + ((Sq-1)&1)*HBUFSZ + hr_*KST;
        float a0=0.f,a1=0.f,a2=0.f,a3=0.f;
        #pragma unroll 8
        for (int k = 0; k < 64; k += 4){
            a0 = fmaf(hr[k],   wout_s[2*k     + hws], a0);
            a1 = fmaf(hr[k+1], wout_s[2*(k+1) + hws], a1);
            a2 = fmaf(hr[k+2], wout_s[2*(k+2) + hws], a2);
            a3 = fmaf(hr[k+3], wout_s[2*(k+3) + hws], a3);
        }
        float a = (a0+a1)+(a2+a3) + b_out[hws];
        float sp = (a > 15.0f) ? a : log1pf(__expf(a));
        sp += 1e-4f;
        int b = row0 + hr_;
        if (hws == 0) out[b*Sq + (Sq-1)] = sp * sc_s[hr_];
        else          out[Bq*Sq + b*Sq + (Sq-1)] = sp;
    }
}

extern "C" void kernel_launch(void* const* d_in, const int* in_sizes, int n_in,
                              void* d_out, int out_size)
{
    (void)in_sizes; (void)n_in; (void)out_size;
    cudaFuncSetAttribute(deepar_kernel,
                         cudaFuncAttributeMaxDynamicSharedMemorySize, SMEM_BYTES);
    deepar_kernel<<<NB, NT, SMEM_BYTES>>>(
        (const float*)d_in[0],   // target
        (const float*)d_in[1],   // covariates
        (const int*)  d_in[2],   // static_cats
        (const float*)d_in[3],   // scale
        (const float*)d_in[4],   // emb0
        (const float*)d_in[5],   // emb1
        (const float*)d_in[6],   // emb2
        (const float*)d_in[7],   // emb3
        (const float*)d_in[8],   // w_ih
        (const float*)d_in[9],   // w_hh
        (const float*)d_in[10],  // bias
        (const float*)d_in[11],  // w_out
        (const float*)d_in[12],  // b_out
        (float*)d_out);
}